// round 1
// baseline (speedup 1.0000x reference)
#include <cuda_runtime.h>
#include <cstdio>

// Problem constants
#define BB   4
#define TT   2048
#define CC   1024
#define HH   16
#define HD   64
#define C3   3072

// Scratch: __device__ globals (no cudaMalloc allowed)
__device__ float g_qkv[(size_t)BB * TT * C3];   // [B,T,3C]
__device__ float g_y  [(size_t)BB * TT * CC];   // [B,T,C]

// ---------------------------------------------------------------------------
// Tiled SGEMM with fused bias: C[M,N] = A[M,K] @ W[K,N] + bias[N]
// BM=128, BN=128, BK=16, 256 threads, 8x8 per thread.
// ---------------------------------------------------------------------------
#define BM 128
#define BN 128
#define BK 16
#define TM 8
#define TN 8

__global__ __launch_bounds__(256) void sgemm_bias_kernel(
    const float* __restrict__ A, const float* __restrict__ W,
    const float* __restrict__ bias, float* __restrict__ C,
    int M, int N, int K)
{
    __shared__ float As[BK][BM];
    __shared__ float Bs[BK][BN];

    const int tid = threadIdx.x;
    const int tx = tid & 15;       // 0..15
    const int ty = tid >> 4;       // 0..15
    const int bm = blockIdx.y * BM;
    const int bn = blockIdx.x * BN;

    float acc[TM][TN];
    #pragma unroll
    for (int i = 0; i < TM; i++)
        #pragma unroll
        for (int j = 0; j < TN; j++) acc[i][j] = 0.f;

    const int arow  = tid >> 2;        // 0..63
    const int acol4 = (tid & 3) * 4;   // 0,4,8,12
    const int brow  = tid >> 5;        // 0..7
    const int bcol4 = (tid & 31) * 4;  // 0..124

    const float* Aptr = A + (size_t)bm * K;
    const float* Wptr = W + bn;

    for (int k0 = 0; k0 < K; k0 += BK) {
        #pragma unroll
        for (int i = 0; i < 2; i++) {
            int r = arow + i * 64;
            float4 a4 = *reinterpret_cast<const float4*>(
                Aptr + (size_t)r * K + k0 + acol4);
            As[acol4 + 0][r] = a4.x;
            As[acol4 + 1][r] = a4.y;
            As[acol4 + 2][r] = a4.z;
            As[acol4 + 3][r] = a4.w;
        }
        #pragma unroll
        for (int i = 0; i < 2; i++) {
            int r = brow + i * 8;
            *reinterpret_cast<float4*>(&Bs[r][bcol4]) =
                *reinterpret_cast<const float4*>(
                    Wptr + (size_t)(k0 + r) * N + bcol4);
        }
        __syncthreads();

        #pragma unroll
        for (int kk = 0; kk < BK; kk++) {
            float af[TM], bf[TN];
            #pragma unroll
            for (int i = 0; i < TM; i++) af[i] = As[kk][ty * TM + i];
            #pragma unroll
            for (int j = 0; j < TN; j++) bf[j] = Bs[kk][tx * TN + j];
            #pragma unroll
            for (int i = 0; i < TM; i++)
                #pragma unroll
                for (int j = 0; j < TN; j++)
                    acc[i][j] += af[i] * bf[j];
        }
        __syncthreads();
    }

    // Epilogue: fused bias, vectorized stores
    #pragma unroll
    for (int i = 0; i < TM; i++) {
        int row = bm + ty * TM + i;
        int col = bn + tx * TN;
        float4 o0, o1;
        o0.x = acc[i][0] + bias[col + 0];
        o0.y = acc[i][1] + bias[col + 1];
        o0.z = acc[i][2] + bias[col + 2];
        o0.w = acc[i][3] + bias[col + 3];
        o1.x = acc[i][4] + bias[col + 4];
        o1.y = acc[i][5] + bias[col + 5];
        o1.z = acc[i][6] + bias[col + 6];
        o1.w = acc[i][7] + bias[col + 7];
        *reinterpret_cast<float4*>(C + (size_t)row * N + col)     = o0;
        *reinterpret_cast<float4*>(C + (size_t)row * N + col + 4) = o1;
    }
}

// ---------------------------------------------------------------------------
// Flash attention (causal). One q-row per thread, BQ=128 rows per block,
// K/V tiles of 32 rows in shared memory. Softmax in log2 domain (single EX2
// per (q,k) pair). Upper triangle skipped at tile granularity.
// grid = (T/128, B*H), block = 128
// ---------------------------------------------------------------------------
__global__ __launch_bounds__(128) void attn_kernel()
{
    __shared__ float Ks[32 * 64];
    __shared__ float Vs[32 * 64];

    const int tid = threadIdx.x;
    const int qt  = blockIdx.x;
    const int bh  = blockIdx.y;
    const int b   = bh >> 4;
    const int h   = bh & 15;
    const int qi  = qt * 128 + tid;

    // load q row into registers, fold in softmax scale * log2(e)
    const float qs = 0.125f * 1.44269504088896f;   // 1/sqrt(64) * log2(e)
    const float* qptr = g_qkv + ((size_t)(b * TT + qi)) * C3 + h * HD;
    float q[64];
    #pragma unroll
    for (int d4 = 0; d4 < 16; d4++) {
        float4 t = reinterpret_cast<const float4*>(qptr)[d4];
        q[4 * d4 + 0] = t.x * qs;
        q[4 * d4 + 1] = t.y * qs;
        q[4 * d4 + 2] = t.z * qs;
        q[4 * d4 + 3] = t.w * qs;
    }

    float acc[64];
    #pragma unroll
    for (int d = 0; d < 64; d++) acc[d] = 0.f;
    float m = -1e30f, l = 0.f;

    const float* Kbase = g_qkv + (size_t)b * TT * C3 + CC + h * HD;
    const float* Vbase = Kbase + CC;

    const int nfull = qt * 4;       // fully-unmasked k tiles
    const int ntot  = qt * 4 + 4;   // total k tiles (last 4 straddle diagonal)

    for (int kt = 0; kt < ntot; kt++) {
        // cooperative load of K/V tile [32,64]
        for (int i = tid; i < 512; i += 128) {
            int r = i >> 4, c = i & 15;
            reinterpret_cast<float4*>(Ks)[i] =
                reinterpret_cast<const float4*>(Kbase + (size_t)(kt * 32 + r) * C3)[c];
            reinterpret_cast<float4*>(Vs)[i] =
                reinterpret_cast<const float4*>(Vbase + (size_t)(kt * 32 + r) * C3)[c];
        }
        __syncthreads();

        // scores for 32 keys
        float s[32];
        #pragma unroll
        for (int j = 0; j < 32; j++) {
            const float4* k4 = reinterpret_cast<const float4*>(Ks + j * 64);
            float s0 = 0.f, s1 = 0.f, s2 = 0.f, s3 = 0.f;
            #pragma unroll
            for (int d4 = 0; d4 < 16; d4++) {
                float4 kv = k4[d4];
                s0 += q[4 * d4 + 0] * kv.x;
                s1 += q[4 * d4 + 1] * kv.y;
                s2 += q[4 * d4 + 2] * kv.z;
                s3 += q[4 * d4 + 3] * kv.w;
            }
            s[j] = (s0 + s1) + (s2 + s3);
        }

        if (kt >= nfull) {   // diagonal tile: causal mask
            #pragma unroll
            for (int j = 0; j < 32; j++)
                if (kt * 32 + j > qi) s[j] = -1e30f;
        }

        // online softmax (base-2)
        float mn = m;
        #pragma unroll
        for (int j = 0; j < 32; j++) mn = fmaxf(mn, s[j]);
        float corr = exp2f(m - mn);
        l *= corr;
        #pragma unroll
        for (int d = 0; d < 64; d++) acc[d] *= corr;

        #pragma unroll
        for (int j = 0; j < 32; j++) {
            float p = exp2f(s[j] - mn);
            l += p;
            const float4* v4 = reinterpret_cast<const float4*>(Vs + j * 64);
            #pragma unroll
            for (int d4 = 0; d4 < 16; d4++) {
                float4 vv = v4[d4];
                acc[4 * d4 + 0] += p * vv.x;
                acc[4 * d4 + 1] += p * vv.y;
                acc[4 * d4 + 2] += p * vv.z;
                acc[4 * d4 + 3] += p * vv.w;
            }
        }
        m = mn;
        __syncthreads();
    }

    const float inv = 1.f / l;
    float* yptr = g_y + ((size_t)(b * TT + qi)) * CC + h * HD;
    #pragma unroll
    for (int d4 = 0; d4 < 16; d4++) {
        float4 o;
        o.x = acc[4 * d4 + 0] * inv;
        o.y = acc[4 * d4 + 1] * inv;
        o.z = acc[4 * d4 + 2] * inv;
        o.w = acc[4 * d4 + 3] * inv;
        reinterpret_cast<float4*>(yptr)[d4] = o;
    }
}

// ---------------------------------------------------------------------------
extern "C" void kernel_launch(void* const* d_in, const int* in_sizes, int n_in,
                              void* d_out, int out_size)
{
    const float* x      = (const float*)d_in[0];   // [B,T,C]
    const float* W_attn = (const float*)d_in[1];   // [C,3C]
    const float* b_attn = (const float*)d_in[2];   // [3C]
    const float* W_proj = (const float*)d_in[3];   // [C,C]
    const float* b_proj = (const float*)d_in[4];   // [C]
    float* out = (float*)d_out;                    // [B,T,C]

    float *qkv, *y;
    cudaGetSymbolAddress((void**)&qkv, g_qkv);
    cudaGetSymbolAddress((void**)&y,   g_y);

    const int M = BB * TT;   // 8192

    // 1) QKV projection: [8192,1024] @ [1024,3072] + b_attn
    {
        dim3 grid(C3 / BN, M / BM);
        sgemm_bias_kernel<<<grid, 256>>>(x, W_attn, b_attn, qkv, M, C3, CC);
    }

    // 2) Causal flash attention per (b,h)
    {
        dim3 grid(TT / 128, BB * HH);
        attn_kernel<<<grid, 128>>>();
    }

    // 3) Output projection: [8192,1024] @ [1024,1024] + b_proj
    {
        dim3 grid(CC / BN, M / BM);
        sgemm_bias_kernel<<<grid, 256>>>(y, W_proj, b_proj, out, M, CC, CC);
    }
}

// round 6
// speedup vs baseline: 1.4392x; 1.4392x over previous
#include <cuda_runtime.h>
#include <cstdint>

// ---------------------------------------------------------------------------
// Problem constants
// ---------------------------------------------------------------------------
#define BBATCH 4
#define TSEQ   2048
#define CEMB   1024
#define NHEAD  16
#define HDIM   64
#define C3     3072
#define MROWS  (BBATCH * TSEQ)   // 8192
#define KDIM   1024

// Scratch (__device__ globals; no cudaMalloc allowed)
__device__ float g_qkv[(size_t)BBATCH * TSEQ * C3];
__device__ float g_y  [(size_t)BBATCH * TSEQ * CEMB];
__device__ float g_WtA[(size_t)C3 * CEMB];     // W_attn^T  [3072,1024]
__device__ float g_WtP[(size_t)CEMB * CEMB];   // W_proj^T  [1024,1024]

// ---------------------------------------------------------------------------
// Helpers (sm_80-compatible only; NO tcgen05 — plain sm_103 target rejects it)
// ---------------------------------------------------------------------------
__device__ __forceinline__ uint32_t smem_u32(const void* p) {
    uint32_t a;
    asm("{ .reg .u64 t; cvta.to.shared.u64 t, %1; cvt.u32.u64 %0, t; }"
        : "=r"(a) : "l"(p));
    return a;
}

__device__ __forceinline__ uint32_t f2tf32(float x) {
    uint32_t o;
    asm("cvt.rna.tf32.f32 %0, %1;" : "=r"(o) : "f"(x));
    return o;
}

#define CP_ASYNC16(dst, src) \
    asm volatile("cp.async.cg.shared.global [%0], [%1], 16;" :: "r"(dst), "l"(src) : "memory")
#define CP_COMMIT() asm volatile("cp.async.commit_group;" ::: "memory")

__device__ __forceinline__ void mma_tf32(
    float& c0, float& c1, float& c2, float& c3,
    uint32_t a0, uint32_t a1, uint32_t a2, uint32_t a3,
    uint32_t b0, uint32_t b1)
{
    asm volatile(
        "mma.sync.aligned.m16n8k8.row.col.f32.tf32.tf32.f32 "
        "{%0,%1,%2,%3}, {%4,%5,%6,%7}, {%8,%9}, {%0,%1,%2,%3};"
        : "+f"(c0), "+f"(c1), "+f"(c2), "+f"(c3)
        : "r"(a0), "r"(a1), "r"(a2), "r"(a3), "r"(b0), "r"(b1));
}

// ---------------------------------------------------------------------------
// Weight transpose: Wt[N][K] = W[K][N]   (block 32x8, tile 32x32)
// ---------------------------------------------------------------------------
__global__ __launch_bounds__(256) void transpose_kernel(
    const float* __restrict__ W, float* __restrict__ Wt, int K, int N)
{
    __shared__ float tile[32][33];
    const int bx = blockIdx.x * 32;   // N offset
    const int by = blockIdx.y * 32;   // K offset
    const int x = threadIdx.x, y0 = threadIdx.y;
    #pragma unroll
    for (int j = 0; j < 32; j += 8)
        tile[y0 + j][x] = W[(size_t)(by + y0 + j) * N + bx + x];
    __syncthreads();
    #pragma unroll
    for (int j = 0; j < 32; j += 8)
        Wt[(size_t)(bx + y0 + j) * K + by + x] = tile[x][y0 + j];
}

// ---------------------------------------------------------------------------
// tf32 mma.sync GEMM: C[M,N] = A[M,1024] @ Wt[N,1024]^T + bias[N]
// 256 thr, BM=BN=128, BK=16, warp grid 2x4 (warp tile 64x32),
// cp.async double-buffer. grid = (N/128, M/128)
// ---------------------------------------------------------------------------
#define NKIT (KDIM / 16)   // 64

__global__ __launch_bounds__(256) void gemm_mma_tf32(
    const float* __restrict__ A, const float* __restrict__ Wt,
    const float* __restrict__ bias, float* __restrict__ C, int N)
{
    __shared__ float As[2][128][20];   // +4 float pad: conflict-free frags,
    __shared__ float Bs[2][128][20];   // 16B-aligned rows (80B stride)

    const int tid  = threadIdx.x;
    const int lane = tid & 31;
    const int wid  = tid >> 5;
    const int wm   = wid >> 2;         // 0..1
    const int wn   = wid & 3;          // 0..3
    const int bm   = blockIdx.y * 128;
    const int bn   = blockIdx.x * 128;

    const int qr = lane >> 2;          // 0..7
    const int kc = lane & 3;           // 0..3

    float acc[4][4][4];
    #pragma unroll
    for (int mf = 0; mf < 4; mf++)
        #pragma unroll
        for (int nf = 0; nf < 4; nf++)
            #pragma unroll
            for (int e = 0; e < 4; e++) acc[mf][nf][e] = 0.f;

    auto load_stage = [&](int s, int i) {
        const int k0 = i * 16;
        #pragma unroll
        for (int j = 0; j < 2; j++) {
            int idx = tid + j * 256;       // 0..511
            int r = idx >> 2, g = idx & 3; // row, 16B granule
            CP_ASYNC16(smem_u32(&As[s][r][g * 4]),
                       A + (size_t)(bm + r) * KDIM + k0 + g * 4);
        }
        #pragma unroll
        for (int j = 0; j < 2; j++) {
            int idx = tid + j * 256;
            int r = idx >> 2, g = idx & 3;
            CP_ASYNC16(smem_u32(&Bs[s][r][g * 4]),
                       Wt + (size_t)(bn + r) * KDIM + k0 + g * 4);
        }
        CP_COMMIT();
    };

    load_stage(0, 0);
    load_stage(1, 1);

    const int r0 = wm * 64 + qr;   // A row base within tile
    const int n0 = wn * 32 + qr;   // B row (n) base within tile

    for (int kt = 0; kt < NKIT; kt++) {
        const int s = kt & 1;
        if (kt == NKIT - 1) asm volatile("cp.async.wait_group 0;" ::: "memory");
        else                asm volatile("cp.async.wait_group 1;" ::: "memory");
        __syncthreads();

        #pragma unroll
        for (int ks = 0; ks < 2; ks++) {
            const int kb = ks * 8 + kc;
            uint32_t af[4][4], bf[4][2];
            #pragma unroll
            for (int mf = 0; mf < 4; mf++) {
                af[mf][0] = f2tf32(As[s][r0 + mf * 16][kb]);
                af[mf][1] = f2tf32(As[s][r0 + mf * 16 + 8][kb]);
                af[mf][2] = f2tf32(As[s][r0 + mf * 16][kb + 4]);
                af[mf][3] = f2tf32(As[s][r0 + mf * 16 + 8][kb + 4]);
            }
            #pragma unroll
            for (int nf = 0; nf < 4; nf++) {
                bf[nf][0] = f2tf32(Bs[s][n0 + nf * 8][kb]);
                bf[nf][1] = f2tf32(Bs[s][n0 + nf * 8][kb + 4]);
            }
            #pragma unroll
            for (int mf = 0; mf < 4; mf++)
                #pragma unroll
                for (int nf = 0; nf < 4; nf++)
                    mma_tf32(acc[mf][nf][0], acc[mf][nf][1],
                             acc[mf][nf][2], acc[mf][nf][3],
                             af[mf][0], af[mf][1], af[mf][2], af[mf][3],
                             bf[nf][0], bf[nf][1]);
        }

        __syncthreads();
        if (kt + 2 < NKIT) load_stage(s, kt + 2);
    }

    // Epilogue: fused bias, float2 stores
    #pragma unroll
    for (int nf = 0; nf < 4; nf++) {
        const int col = bn + wn * 32 + nf * 8 + kc * 2;
        const float2 bv = *reinterpret_cast<const float2*>(bias + col);
        #pragma unroll
        for (int mf = 0; mf < 4; mf++) {
            const int row = bm + wm * 64 + mf * 16 + qr;
            float2 v0 = make_float2(acc[mf][nf][0] + bv.x,
                                    acc[mf][nf][1] + bv.y);
            float2 v1 = make_float2(acc[mf][nf][2] + bv.x,
                                    acc[mf][nf][3] + bv.y);
            *reinterpret_cast<float2*>(C + (size_t)row * N + col)       = v0;
            *reinterpret_cast<float2*>(C + (size_t)(row + 8) * N + col) = v1;
        }
    }
}

// ---------------------------------------------------------------------------
// Flash attention (causal), fp32 scalar — verified in round 1
// grid = (T/128, B*H), block = 128
// ---------------------------------------------------------------------------
__global__ __launch_bounds__(128) void attn_kernel()
{
    __shared__ float Ks[32 * 64];
    __shared__ float Vs[32 * 64];

    const int tid = threadIdx.x;
    const int qt  = blockIdx.x;
    const int bh  = blockIdx.y;
    const int b   = bh >> 4;
    const int h   = bh & 15;
    const int qi  = qt * 128 + tid;

    const float qs = 0.125f * 1.44269504088896f;
    const float* qptr = g_qkv + ((size_t)(b * TSEQ + qi)) * C3 + h * HDIM;
    float q[64];
    #pragma unroll
    for (int d4 = 0; d4 < 16; d4++) {
        float4 t = reinterpret_cast<const float4*>(qptr)[d4];
        q[4 * d4 + 0] = t.x * qs;
        q[4 * d4 + 1] = t.y * qs;
        q[4 * d4 + 2] = t.z * qs;
        q[4 * d4 + 3] = t.w * qs;
    }

    float acc[64];
    #pragma unroll
    for (int d = 0; d < 64; d++) acc[d] = 0.f;
    float m = -1e30f, l = 0.f;

    const float* Kbase = g_qkv + (size_t)b * TSEQ * C3 + CEMB + h * HDIM;
    const float* Vbase = Kbase + CEMB;

    const int nfull = qt * 4;
    const int ntot  = qt * 4 + 4;

    for (int kt = 0; kt < ntot; kt++) {
        for (int i = tid; i < 512; i += 128) {
            int r = i >> 4, c = i & 15;
            reinterpret_cast<float4*>(Ks)[i] =
                reinterpret_cast<const float4*>(Kbase + (size_t)(kt * 32 + r) * C3)[c];
            reinterpret_cast<float4*>(Vs)[i] =
                reinterpret_cast<const float4*>(Vbase + (size_t)(kt * 32 + r) * C3)[c];
        }
        __syncthreads();

        float s[32];
        #pragma unroll
        for (int j = 0; j < 32; j++) {
            const float4* k4 = reinterpret_cast<const float4*>(Ks + j * 64);
            float s0 = 0.f, s1 = 0.f, s2 = 0.f, s3 = 0.f;
            #pragma unroll
            for (int d4 = 0; d4 < 16; d4++) {
                float4 kv = k4[d4];
                s0 += q[4 * d4 + 0] * kv.x;
                s1 += q[4 * d4 + 1] * kv.y;
                s2 += q[4 * d4 + 2] * kv.z;
                s3 += q[4 * d4 + 3] * kv.w;
            }
            s[j] = (s0 + s1) + (s2 + s3);
        }

        if (kt >= nfull) {
            #pragma unroll
            for (int j = 0; j < 32; j++)
                if (kt * 32 + j > qi) s[j] = -1e30f;
        }

        float mn = m;
        #pragma unroll
        for (int j = 0; j < 32; j++) mn = fmaxf(mn, s[j]);
        float corr = exp2f(m - mn);
        l *= corr;
        #pragma unroll
        for (int d = 0; d < 64; d++) acc[d] *= corr;

        #pragma unroll
        for (int j = 0; j < 32; j++) {
            float p = exp2f(s[j] - mn);
            l += p;
            const float4* v4 = reinterpret_cast<const float4*>(Vs + j * 64);
            #pragma unroll
            for (int d4 = 0; d4 < 16; d4++) {
                float4 vv = v4[d4];
                acc[4 * d4 + 0] += p * vv.x;
                acc[4 * d4 + 1] += p * vv.y;
                acc[4 * d4 + 2] += p * vv.z;
                acc[4 * d4 + 3] += p * vv.w;
            }
        }
        m = mn;
        __syncthreads();
    }

    const float inv = 1.f / l;
    float* yptr = g_y + ((size_t)(b * TSEQ + qi)) * CEMB + h * HDIM;
    #pragma unroll
    for (int d4 = 0; d4 < 16; d4++) {
        float4 o;
        o.x = acc[4 * d4 + 0] * inv;
        o.y = acc[4 * d4 + 1] * inv;
        o.z = acc[4 * d4 + 2] * inv;
        o.w = acc[4 * d4 + 3] * inv;
        reinterpret_cast<float4*>(yptr)[d4] = o;
    }
}

// ---------------------------------------------------------------------------
extern "C" void kernel_launch(void* const* d_in, const int* in_sizes, int n_in,
                              void* d_out, int out_size)
{
    const float* x      = (const float*)d_in[0];   // [B,T,C]
    const float* W_attn = (const float*)d_in[1];   // [C,3C]
    const float* b_attn = (const float*)d_in[2];   // [3C]
    const float* W_proj = (const float*)d_in[3];   // [C,C]
    const float* b_proj = (const float*)d_in[4];   // [C]
    float* out = (float*)d_out;                    // [B,T,C]

    float *qkv, *y, *wtA, *wtP;
    cudaGetSymbolAddress((void**)&qkv, g_qkv);
    cudaGetSymbolAddress((void**)&y,   g_y);
    cudaGetSymbolAddress((void**)&wtA, g_WtA);
    cudaGetSymbolAddress((void**)&wtP, g_WtP);

    // 0) transpose weights into [N,K] layout
    {
        dim3 blk(32, 8);
        transpose_kernel<<<dim3(C3 / 32, CEMB / 32), blk>>>(W_attn, wtA, CEMB, C3);
        transpose_kernel<<<dim3(CEMB / 32, CEMB / 32), blk>>>(W_proj, wtP, CEMB, CEMB);
    }

    // 1) QKV projection (tf32 mma.sync tensor cores)
    gemm_mma_tf32<<<dim3(C3 / 128, MROWS / 128), 256>>>(x, wtA, b_attn, qkv, C3);

    // 2) Causal flash attention
    attn_kernel<<<dim3(TSEQ / 128, BBATCH * NHEAD), 128>>>();

    // 3) Output projection (tf32 mma.sync tensor cores)
    gemm_mma_tf32<<<dim3(CEMB / 128, MROWS / 128), 256>>>(y, wtP, b_proj, out, CEMB);
}